// round 2
// baseline (speedup 1.0000x reference)
#include <cuda_runtime.h>
#include <cstdint>

// ---------------------------------------------------------------------------
// Problem constants: B=64, T=4, N=6, IMG=128, CIN=3, VE=64, D=256, P=4, R=8
// ---------------------------------------------------------------------------
#define NB 64
#define NT 4
#define NN 6
#define NBT 256            // B*T
#define NROI 1536          // B*T*N
#define NROW 384           // B*N
#define ND 256
#define SD (NROW*ND)
#define NROLL 8

typedef unsigned long long ull;

__device__ __forceinline__ ull pk(float lo, float hi) {
    ull r; asm("mov.b64 %0,{%1,%2};" : "=l"(r) : "f"(lo), "f"(hi)); return r;
}
__device__ __forceinline__ float2 upk(ull v) {
    float2 f; asm("mov.b64 {%0,%1},%2;" : "=f"(f.x), "=f"(f.y) : "l"(v)); return f;
}
__device__ __forceinline__ void fma2(ull& d, ull a, ull b) {
    asm("fma.rn.f32x2 %0,%1,%2,%0;" : "+l"(d) : "l"(a), "l"(b));
}

// ---------------------------------------------------------------------------
// Device scratch
// ---------------------------------------------------------------------------
__device__ float g_f1[(size_t)NBT * 64 * 64 * 64];
__device__ float g_f2[(size_t)NBT * 64 * 32 * 32];
__device__ float g_pool [NROI * 1024];
__device__ float g_obj  [NROI * ND];
__device__ float g_emb1 [NROI * ND];
__device__ float g_emb2 [NROI * ND];
__device__ float g_sttmp[NROI * ND];
__device__ float g_O[4 * SD];
__device__ float g_P[8 * SD];
__device__ float g_selfd[4 * SD];
__device__ float g_u[4 * SD];
__device__ float g_v[4 * SD];
__device__ float g_t[4 * SD];
__device__ float g_a[4 * SD];
__device__ float g_cs[NROW * 1024];
__device__ float g_aggp[4 * SD];
__device__ float g_r[NROW];

// ---------------------------------------------------------------------------
__global__ void r_kernel(const float* __restrict__ rois) {
    int i = blockIdx.x * 128 + threadIdx.x;
    if (i >= NROW) return;
    int b = i / NN, n = i % NN;
    float s = 0.f;
    for (int t = 0; t < NT; ++t) {
        const float* ro = rois + (size_t)(((b * NT + t) * NN) + n) * 5;
        s += ((ro[4] - ro[2]) * 0.5f + (ro[3] - ro[1]) * 0.5f) * 0.5f;
    }
    g_r[i] = s * 0.25f;
}

// ---------------------------------------------------------------------------
// conv1: (256,3,128,128) -> relu -> (256,64,64,64), 3x3 s2 SAME (pad hi only)
// grid (64, 256), block 256 = 16 oxt x 16 cot, micro: co-pairs x 4 ox (FFMA2)
// input stored duplicated {v,v} so the dup operand comes from one LDS.64
// ---------------------------------------------------------------------------
__global__ void conv1_kernel(const float* __restrict__ x,
                             const float* __restrict__ w1,
                             const float* __restrict__ b1) {
    int oy = blockIdx.x, bt = blockIdx.y;
    __shared__ float ins2[3 * 3 * 264];   // [ci][kh][2*132] duplicated pairs
    __shared__ float ws[27 * 64];         // [off][co]
    __shared__ float bs[64];
    int tid = threadIdx.x;
    for (int i = tid; i < 3 * 3 * 132; i += 256) {
        int ci = i / 396, rem = i % 396, kh = rem / 132, ix = rem % 132;
        int iy = 2 * oy + kh;
        float v = 0.f;
        if (iy < 128 && ix < 128)
            v = x[(((size_t)bt * 3 + ci) * 128 + iy) * 128 + ix];
        *(ull*)&ins2[(ci * 3 + kh) * 264 + 2 * ix] = pk(v, v);
    }
    for (int i = tid; i < 1728; i += 256) {
        int co = i / 27, off = i % 27;
        ws[off * 64 + co] = w1[i];
    }
    if (tid < 64) bs[tid] = b1[tid];
    __syncthreads();

    int oxt = tid & 15, cot = tid >> 4;
    int ox0 = oxt * 4, co0 = cot * 4;
    ull acc[2][4] = {};
#pragma unroll
    for (int ci = 0; ci < 3; ++ci)
#pragma unroll
        for (int kh = 0; kh < 3; ++kh) {
            const float* ibase = &ins2[(ci * 3 + kh) * 264 + 4 * ox0];
#pragma unroll
            for (int kw = 0; kw < 3; ++kw) {
                ulonglong2 wp = *(const ulonglong2*)&ws[(ci * 9 + kh * 3 + kw) * 64 + co0];
#pragma unroll
                for (int dx = 0; dx < 4; ++dx) {
                    ull vd = *(const ull*)&ibase[4 * dx + 2 * kw];
                    fma2(acc[0][dx], wp.x, vd);
                    fma2(acc[1][dx], wp.y, vd);
                }
            }
        }
#pragma unroll
    for (int p = 0; p < 2; ++p) {
        float2 f0 = upk(acc[p][0]), f1 = upk(acc[p][1]);
        float2 f2 = upk(acc[p][2]), f3 = upk(acc[p][3]);
        int co = co0 + 2 * p;
        float ba = bs[co], bb = bs[co + 1];
        float4 oa, ob;
        oa.x = fmaxf(f0.x + ba, 0.f); oa.y = fmaxf(f1.x + ba, 0.f);
        oa.z = fmaxf(f2.x + ba, 0.f); oa.w = fmaxf(f3.x + ba, 0.f);
        ob.x = fmaxf(f0.y + bb, 0.f); ob.y = fmaxf(f1.y + bb, 0.f);
        ob.z = fmaxf(f2.y + bb, 0.f); ob.w = fmaxf(f3.y + bb, 0.f);
        *(float4*)&g_f1[(((size_t)bt * 64 + co) * 64 + oy) * 64 + ox0] = oa;
        *(float4*)&g_f1[(((size_t)bt * 64 + co + 1) * 64 + oy) * 64 + ox0] = ob;
    }
}

// ---------------------------------------------------------------------------
// conv2: (256,64,64,64) -> relu -> (256,64,32,32), 3x3 s2 SAME
// grid (32, 256), block 128 = 8 oxt x 16 cot, ci chunks of 8, FFMA2
// ---------------------------------------------------------------------------
__global__ void conv2_kernel(const float* __restrict__ w2,
                             const float* __restrict__ b2) {
    int oy = blockIdx.x, bt = blockIdx.y;
    __shared__ float ins2[8 * 3 * 136];  // duplicated pairs, 68 pixels/row
    __shared__ float ws[8 * 9 * 64];
    int tid = threadIdx.x;
    int oxt = tid & 7, cot = tid >> 3;
    int ox0 = oxt * 4, co0 = cot * 4;
    ull acc[2][4] = {};
#pragma unroll 1
    for (int cc = 0; cc < 8; ++cc) {
        __syncthreads();
        for (int i = tid; i < 8 * 3 * 68; i += 128) {
            int ci = i / 204, rem = i % 204, row = rem / 68, ix = rem % 68;
            int iy = 2 * oy + row;
            int cig = cc * 8 + ci;
            float v = 0.f;
            if (ix < 64 && iy < 64)
                v = g_f1[(((size_t)bt * 64 + cig) * 64 + iy) * 64 + ix];
            *(ull*)&ins2[(ci * 3 + row) * 136 + 2 * ix] = pk(v, v);
        }
        for (int i = tid; i < 64 * 72; i += 128) {
            int co = i / 72, off = i % 72;
            ws[off * 64 + co] = w2[(size_t)co * 576 + cc * 72 + off];
        }
        __syncthreads();
#pragma unroll
        for (int ci = 0; ci < 8; ++ci)
#pragma unroll
            for (int kh = 0; kh < 3; ++kh) {
                const float* ibase = &ins2[(ci * 3 + kh) * 136 + 4 * ox0];
#pragma unroll
                for (int kw = 0; kw < 3; ++kw) {
                    ulonglong2 wp = *(const ulonglong2*)&ws[((ci * 3 + kh) * 3 + kw) * 64 + co0];
#pragma unroll
                    for (int dx = 0; dx < 4; ++dx) {
                        ull vd = *(const ull*)&ibase[4 * dx + 2 * kw];
                        fma2(acc[0][dx], wp.x, vd);
                        fma2(acc[1][dx], wp.y, vd);
                    }
                }
            }
    }
#pragma unroll
    for (int p = 0; p < 2; ++p) {
        float2 f0 = upk(acc[p][0]), f1 = upk(acc[p][1]);
        float2 f2 = upk(acc[p][2]), f3 = upk(acc[p][3]);
        int co = co0 + 2 * p;
        float ba = b2[co], bb = b2[co + 1];
        float4 oa, ob;
        oa.x = fmaxf(f0.x + ba, 0.f); oa.y = fmaxf(f1.x + ba, 0.f);
        oa.z = fmaxf(f2.x + ba, 0.f); oa.w = fmaxf(f3.x + ba, 0.f);
        ob.x = fmaxf(f0.y + bb, 0.f); ob.y = fmaxf(f1.y + bb, 0.f);
        ob.z = fmaxf(f2.y + bb, 0.f); ob.w = fmaxf(f3.y + bb, 0.f);
        *(float4*)&g_f2[(((size_t)bt * 64 + co) * 32 + oy) * 32 + ox0] = oa;
        *(float4*)&g_f2[(((size_t)bt * 64 + co + 1) * 32 + oy) * 32 + ox0] = ob;
    }
}

// ---------------------------------------------------------------------------
__global__ void roi_kernel(const float* __restrict__ rois) {
    int r = blockIdx.x;
    __shared__ float ro[5];
    if (threadIdx.x < 5) ro[threadIdx.x] = rois[(size_t)r * 5 + threadIdx.x];
    __syncthreads();
    int bt = (int)ro[0];
    float x1 = ro[1] * 0.25f, y1 = ro[2] * 0.25f;
    float x2 = ro[3] * 0.25f, y2 = ro[4] * 0.25f;
    float bw = fmaxf(x2 - x1, 1.f) * 0.25f;
    float bh = fmaxf(y2 - y1, 1.f) * 0.25f;
    for (int idx = threadIdx.x; idx < 1024; idx += 256) {
        int c = idx >> 4, py = (idx >> 2) & 3, px = idx & 3;
        float sx = x1 + bw * (px + 0.5f);
        float sy = y1 + bh * (py + 0.5f);
        float x0f = fminf(fmaxf(floorf(sx), 0.f), 31.f);
        float y0f = fminf(fmaxf(floorf(sy), 0.f), 31.f);
        float lx = fminf(fmaxf(sx - x0f, 0.f), 1.f);
        float ly = fminf(fmaxf(sy - y0f, 0.f), 1.f);
        int x0 = (int)x0f, y0 = (int)y0f;
        int x1i = min(x0 + 1, 31), y1i = min(y0 + 1, 31);
        const float* f = &g_f2[((size_t)bt * 64 + c) * 1024];
        float v00 = f[y0 * 32 + x0];
        float v01 = f[y0 * 32 + x1i];
        float v10 = f[y1i * 32 + x0];
        float v11 = f[y1i * 32 + x1i];
        float val = v00 * (1.f - ly) * (1.f - lx) + v01 * (1.f - ly) * lx +
                    v10 * ly * (1.f - lx) + v11 * ly * lx;
        g_pool[(size_t)r * 1024 + idx] = val;
    }
}

// ---------------------------------------------------------------------------
__global__ void emb0_kernel(const float* __restrict__ sc,
                            const float* __restrict__ w,
                            const float* __restrict__ b) {
    int row = blockIdx.x, c = threadIdx.x;
    float x0 = sc[(size_t)row * 2], x1 = sc[(size_t)row * 2 + 1];
    float e = fmaf(w[c * 2], x0, fmaf(w[c * 2 + 1], x1, b[c]));
    g_emb1[(size_t)row * ND + c] = fmaxf(e, 0.f);
}

__global__ void rearr_kernel() {
    int i = blockIdx.x * 256 + threadIdx.x;
    int d = i & 255;
    int m = i >> 8;
    int n = m % NN;
    int t = (m / NN) % NT;
    int b = m / (NN * NT);
    g_O[((size_t)t * NROW + b * NN + n) * ND + d] = g_sttmp[i];
}

// ---------------------------------------------------------------------------
// GEMM: 32x64 tile, 128 threads, micro 4x4, FFMA2 via dup-stored A in smem.
// C[m,n] = act( sum_k A(m,k) * W[n,k] + bias[n] ); A = concat(A1,A2) cols.
// ---------------------------------------------------------------------------
struct GemmArgs {
    const float* A1[12];
    const float* A2[12];
    const float* W[12];
    const float* Bias[12];
    float*       C[12];
    int          ldw[12];
    int lda1, lda2, ldc, K1, K2, relu;
};

__global__ void gemm_nt_kernel(GemmArgs g) {
    const int z = blockIdx.z;
    const float* __restrict__ A1 = g.A1[z];
    const float* __restrict__ A2 = g.A2[z];
    const float* __restrict__ W  = g.W[z];
    const float* __restrict__ Bv = g.Bias[z];
    float* __restrict__ C = g.C[z];
    const int ldw = g.ldw[z];
    const int m0 = blockIdx.x * 32, n0 = blockIdx.y * 64;
    __shared__ float As2[16 * 68];   // [k][2m] duplicated pairs (64 + pad 4)
    __shared__ float Ws[16 * 68];    // [k][n]  (64 + pad 4)
    const int tid = threadIdx.x;     // 128
    const int lr = tid >> 2, lc = (tid & 3) * 4;
    const int ty = tid >> 4, tx = tid & 15;
    ull acc[4][2] = {};
    const int K = g.K1 + g.K2;
    for (int kk = 0; kk < K; kk += 16) {
        int col = kk + lc;
        const float* ap;
        if (col < g.K1) ap = A1 + (size_t)(m0 + lr) * g.lda1 + col;
        else            ap = A2 + (size_t)(m0 + lr) * g.lda2 + (col - g.K1);
        float4 av = *(const float4*)ap;
        float4 w0 = *(const float4*)(W + (size_t)(n0 + lr) * ldw + col);
        float4 w1 = *(const float4*)(W + (size_t)(n0 + lr + 32) * ldw + col);
        *(ull*)&As2[(lc + 0) * 68 + 2 * lr] = pk(av.x, av.x);
        *(ull*)&As2[(lc + 1) * 68 + 2 * lr] = pk(av.y, av.y);
        *(ull*)&As2[(lc + 2) * 68 + 2 * lr] = pk(av.z, av.z);
        *(ull*)&As2[(lc + 3) * 68 + 2 * lr] = pk(av.w, av.w);
        Ws[(lc + 0) * 68 + lr] = w0.x; Ws[(lc + 1) * 68 + lr] = w0.y;
        Ws[(lc + 2) * 68 + lr] = w0.z; Ws[(lc + 3) * 68 + lr] = w0.w;
        Ws[(lc + 0) * 68 + lr + 32] = w1.x; Ws[(lc + 1) * 68 + lr + 32] = w1.y;
        Ws[(lc + 2) * 68 + lr + 32] = w1.z; Ws[(lc + 3) * 68 + lr + 32] = w1.w;
        __syncthreads();
#pragma unroll
        for (int k = 0; k < 16; ++k) {
            ulonglong2 a01 = *(const ulonglong2*)&As2[k * 68 + 8 * ty];
            ulonglong2 a23 = *(const ulonglong2*)&As2[k * 68 + 8 * ty + 4];
            ulonglong2 bv  = *(const ulonglong2*)&Ws [k * 68 + 4 * tx];
            fma2(acc[0][0], a01.x, bv.x); fma2(acc[0][1], a01.x, bv.y);
            fma2(acc[1][0], a01.y, bv.x); fma2(acc[1][1], a01.y, bv.y);
            fma2(acc[2][0], a23.x, bv.x); fma2(acc[2][1], a23.x, bv.y);
            fma2(acc[3][0], a23.y, bv.x); fma2(acc[3][1], a23.y, bv.y);
        }
        __syncthreads();
    }
    int n = n0 + tx * 4;
    float b0 = 0.f, b1 = 0.f, b2 = 0.f, b3 = 0.f;
    if (Bv) { b0 = Bv[n]; b1 = Bv[n + 1]; b2 = Bv[n + 2]; b3 = Bv[n + 3]; }
#pragma unroll
    for (int i = 0; i < 4; ++i) {
        float2 p01 = upk(acc[i][0]);
        float2 p23 = upk(acc[i][1]);
        float4 o;
        o.x = p01.x + b0; o.y = p01.y + b1;
        o.z = p23.x + b2; o.w = p23.y + b3;
        if (g.relu) {
            o.x = fmaxf(o.x, 0.f); o.y = fmaxf(o.y, 0.f);
            o.z = fmaxf(o.z, 0.f); o.w = fmaxf(o.w, 0.f);
        }
        *(float4*)(C + (size_t)(m0 + ty * 4 + i) * g.ldc + n) = o;
    }
}

// ---------------------------------------------------------------------------
// masked relational sum
// ---------------------------------------------------------------------------
struct MaskArgs {
    const float* coor[4];
    int cbs[4];
    int cns[4];
    const float* relb;
};

__global__ void mask_relsum_kernel(MaskArgs ma) {
    int b = blockIdx.x, k = blockIdx.y;
    __shared__ float cx[NN], cy[NN], rr[NN], cnt[NN];
    __shared__ int   mask[NN][NN];
    int tid = threadIdx.x;
    if (tid < NN) {
        const float* cp = ma.coor[k] + (size_t)b * ma.cbs[k] + tid * ma.cns[k];
        cx[tid] = cp[0];
        cy[tid] = cp[1];
        rr[tid] = g_r[b * NN + tid];
    }
    __syncthreads();
    if (tid < NN * NN) {
        int i = tid / NN, j = tid % NN;
        float dx = cx[i] - cx[j], dy = cy[i] - cy[j];
        float dist = sqrtf(dx * dx + dy * dy);
        mask[i][j] = (i != j) && (dist <= rr[i] + rr[j]);
    }
    __syncthreads();
    if (tid < NN) {
        int c = 0;
        for (int j = 0; j < NN; ++j) c += mask[tid][j];
        cnt[tid] = (float)c;
    }
    __syncthreads();
    int d = tid;
    float rb = ma.relb[k * ND + d];
    size_t base = (size_t)k * SD + (size_t)b * NN * ND;
    float vv[NN];
#pragma unroll
    for (int j = 0; j < NN; ++j) vv[j] = g_v[base + j * ND + d];
#pragma unroll
    for (int i = 0; i < NN; ++i) {
        float acc = g_selfd[base + i * ND + d] + cnt[i] * (g_u[base + i * ND + d] + rb);
#pragma unroll
        for (int j = 0; j < NN; ++j)
            if (mask[i][j]) acc += vv[j];
        g_t[base + i * ND + d] = acc;
    }
}

// ---------------------------------------------------------------------------
// agg_finish: sum 4 split-K partials + bias -> s (state), then dec -> bbox.
// grid 384, block 256. One row per block.
// ---------------------------------------------------------------------------
__global__ void agg_finish_kernel(const float* __restrict__ aggb,
                                  const float* __restrict__ dw,
                                  const float* __restrict__ db,
                                  float* __restrict__ out,
                                  float* __restrict__ Pst, int it) {
    int row = blockIdx.x, tid = threadIdx.x;
    size_t off = (size_t)row * ND + tid;
    float s = aggb[tid] + g_aggp[off] + g_aggp[SD + off] +
              g_aggp[2 * SD + off] + g_aggp[3 * SD + off];
    Pst[off] = s;
    float p0 = s * dw[tid];
    float p1 = s * dw[256 + tid];
    float p2 = s * dw[512 + tid];
    float p3 = s * dw[768 + tid];
#pragma unroll
    for (int o = 16; o > 0; o >>= 1) {
        p0 += __shfl_down_sync(0xffffffffu, p0, o);
        p1 += __shfl_down_sync(0xffffffffu, p1, o);
        p2 += __shfl_down_sync(0xffffffffu, p2, o);
        p3 += __shfl_down_sync(0xffffffffu, p3, o);
    }
    __shared__ float sw[8][4];
    int wid = tid >> 5, lane = tid & 31;
    if (lane == 0) { sw[wid][0] = p0; sw[wid][1] = p1; sw[wid][2] = p2; sw[wid][3] = p3; }
    __syncthreads();
    if (tid < 4) {
        float acc = db[tid];
#pragma unroll
        for (int w = 0; w < 8; ++w) acc += sw[w][tid];
        int b = row / NN, n = row % NN;
        out[(size_t)b * (NROLL * NN * 4) + it * (NN * 4) + n * 4 + tid] = acc;
    }
}

// ---------------------------------------------------------------------------
// Host launcher
// ---------------------------------------------------------------------------
static void launch_gemm(int numZ, int M, int K1, int K2,
                        const float* const* A1, int lda1,
                        const float* const* A2, int lda2,
                        const float* const* W, const int* ldw,
                        const float* const* Bias,
                        float* const* C, int ldc, int relu) {
    GemmArgs ga;
    for (int z = 0; z < numZ; ++z) {
        ga.A1[z] = A1[z];
        ga.A2[z] = A2 ? A2[z] : A1[z];
        ga.W[z] = W[z];
        ga.Bias[z] = Bias ? Bias[z] : nullptr;
        ga.C[z] = C[z];
        ga.ldw[z] = ldw[z];
    }
    for (int z = numZ; z < 12; ++z) {
        ga.A1[z] = ga.A1[0]; ga.A2[z] = ga.A2[0]; ga.W[z] = ga.W[0];
        ga.Bias[z] = nullptr; ga.C[z] = ga.C[0]; ga.ldw[z] = ga.ldw[0];
    }
    ga.lda1 = lda1; ga.lda2 = lda2; ga.ldc = ldc;
    ga.K1 = K1; ga.K2 = K2; ga.relu = relu;
    dim3 grid(M / 32, 4, numZ);
    gemm_nt_kernel<<<grid, 128>>>(ga);
}

extern "C" void kernel_launch(void* const* d_in, const int* in_sizes, int n_in,
                              void* d_out, int out_size) {
    const float* x       = (const float*)d_in[0];
    const float* rois    = (const float*)d_in[1];
    const float* src     = (const float*)d_in[2];
    const float* w_conv1 = (const float*)d_in[3];
    const float* b_conv1 = (const float*)d_in[4];
    const float* w_conv2 = (const float*)d_in[5];
    const float* b_conv2 = (const float*)d_in[6];
    const float* fc0_w   = (const float*)d_in[7];
    const float* fc0_b   = (const float*)d_in[8];
    const float* fc0c_w  = (const float*)d_in[9];
    const float* fc0c_b  = (const float*)d_in[10];
    const float* fc1c_w  = (const float*)d_in[11];
    const float* fc1c_b  = (const float*)d_in[12];
    const float* red_w   = (const float*)d_in[13];
    const float* red_b   = (const float*)d_in[14];
    const float* g_self_w = (const float*)d_in[15];
    const float* g_self_b = (const float*)d_in[16];
    const float* g_rel_w  = (const float*)d_in[17];
    const float* g_rel_b  = (const float*)d_in[18];
    const float* g_aff_w  = (const float*)d_in[19];
    const float* g_aff_b  = (const float*)d_in[20];
    const float* g_out_w  = (const float*)d_in[21];
    const float* g_out_b  = (const float*)d_in[22];
    const float* agg_w   = (const float*)d_in[23];
    const float* agg_b   = (const float*)d_in[24];
    const float* dec_w   = (const float*)d_in[25];
    const float* dec_b   = (const float*)d_in[26];
    float* outp = (float*)d_out;

    float *pool, *obj, *emb1, *emb2, *sttmp, *O, *P, *selfd, *u, *v, *t, *a, *cs, *aggp;
    cudaGetSymbolAddress((void**)&pool,  g_pool);
    cudaGetSymbolAddress((void**)&obj,   g_obj);
    cudaGetSymbolAddress((void**)&emb1,  g_emb1);
    cudaGetSymbolAddress((void**)&emb2,  g_emb2);
    cudaGetSymbolAddress((void**)&sttmp, g_sttmp);
    cudaGetSymbolAddress((void**)&O,     g_O);
    cudaGetSymbolAddress((void**)&P,     g_P);
    cudaGetSymbolAddress((void**)&selfd, g_selfd);
    cudaGetSymbolAddress((void**)&u,     g_u);
    cudaGetSymbolAddress((void**)&v,     g_v);
    cudaGetSymbolAddress((void**)&t,     g_t);
    cudaGetSymbolAddress((void**)&a,     g_a);
    cudaGetSymbolAddress((void**)&cs,    g_cs);
    cudaGetSymbolAddress((void**)&aggp,  g_aggp);

    // ---- preamble ----
    r_kernel<<<3, 128>>>(rois);
    conv1_kernel<<<dim3(64, NBT), 256>>>(x, w_conv1, b_conv1);
    conv2_kernel<<<dim3(32, NBT), 128>>>(w_conv2, b_conv2);
    roi_kernel<<<NROI, 256>>>(rois);
    emb0_kernel<<<NROI, 256>>>(src, fc0c_w, fc0c_b);

    {   // fc1c
        const float* A1[1] = { emb1 };
        const float* W[1] = { fc1c_w }; int ldw[1] = { 256 };
        const float* B[1] = { fc1c_b };
        float* C[1] = { emb2 };
        launch_gemm(1, NROI, 256, 0, A1, 256, nullptr, 0, W, ldw, B, C, ND, 1);
    }
    {   // fc0
        const float* A1[1] = { pool };
        const float* W[1] = { fc0_w }; int ldw[1] = { 1024 };
        const float* B[1] = { fc0_b };
        float* C[1] = { obj };
        launch_gemm(1, NROI, 1024, 0, A1, 1024, nullptr, 0, W, ldw, B, C, ND, 1);
    }
    {   // red
        const float* A1[1] = { obj };
        const float* A2[1] = { emb2 };
        const float* W[1] = { red_w }; int ldw[1] = { 512 };
        const float* B[1] = { red_b };
        float* C[1] = { sttmp };
        launch_gemm(1, NROI, 256, 256, A1, 256, A2, 256, W, ldw, B, C, ND, 1);
    }
    rearr_kernel<<<NROI, 256>>>();

    // ---- rollouts ----
    for (int it = 0; it < NROLL; ++it) {
        const float* st[4];
        MaskArgs ma;
        for (int k = 0; k < 4; ++k) {
            int idx = it + k;
            st[k] = (idx < 4) ? (O + (size_t)idx * SD) : (P + (size_t)(idx - 4) * SD);
            if (idx < 4) {
                ma.coor[k] = src + idx * (NN * 2);
                ma.cbs[k] = NT * NN * 2;
                ma.cns[k] = 2;
            } else {
                ma.coor[k] = outp + (idx - 4) * (NN * 4) + 2;
                ma.cbs[k] = NROLL * NN * 4;
                ma.cns[k] = 4;
            }
        }
        ma.relb = g_rel_b;

        {   // selfd / u / v : 12-way batched GEMM
            const float* A1[12]; const float* W[12]; const float* B[12];
            float* C[12]; int ldw[12];
            for (int z = 0; z < 12; ++z) {
                int k = z & 3, kind = z >> 2;
                A1[z] = st[k];
                if (kind == 0)      { W[z] = g_self_w + (size_t)k * 65536;       ldw[z] = 256; B[z] = g_self_b + k * 256; C[z] = selfd + (size_t)k * SD; }
                else if (kind == 1) { W[z] = g_rel_w + (size_t)k * 131072;       ldw[z] = 512; B[z] = nullptr;            C[z] = u + (size_t)k * SD; }
                else                { W[z] = g_rel_w + (size_t)k * 131072 + 256; ldw[z] = 512; B[z] = nullptr;            C[z] = v + (size_t)k * SD; }
            }
            launch_gemm(12, NROW, 256, 0, A1, 256, nullptr, 0, W, ldw, B, C, ND, 0);
        }
        mask_relsum_kernel<<<dim3(NB, 4), 256>>>(ma);
        {   // aff
            const float* A1[4]; const float* W[4]; const float* B[4];
            float* C[4]; int ldw[4];
            for (int k = 0; k < 4; ++k) {
                A1[k] = t + (size_t)k * SD;
                W[k] = g_aff_w + (size_t)k * 65536; ldw[k] = 256;
                B[k] = g_aff_b + k * 256;
                C[k] = a + (size_t)k * SD;
            }
            launch_gemm(4, NROW, 256, 0, A1, 256, nullptr, 0, W, ldw, B, C, ND, 1);
        }
        {   // out: cs_k = relu(concat(a, state) @ ow.T + b)
            const float* A1[4]; const float* A2[4]; const float* W[4]; const float* B[4];
            float* C[4]; int ldw[4];
            for (int k = 0; k < 4; ++k) {
                A1[k] = a + (size_t)k * SD;
                A2[k] = st[k];
                W[k] = g_out_w + (size_t)k * 131072; ldw[k] = 512;
                B[k] = g_out_b + k * 256;
                C[k] = cs + k * 256;
            }
            launch_gemm(4, NROW, 256, 256, A1, 256, A2, 256, W, ldw, B, C, 1024, 1);
        }
        {   // agg split-K x4 -> partials
            const float* A1[4]; const float* W[4]; const float* B[4];
            float* C[4]; int ldw[4];
            for (int z = 0; z < 4; ++z) {
                A1[z] = cs + z * 256;
                W[z] = agg_w + z * 256; ldw[z] = 1024;
                B[z] = nullptr;
                C[z] = aggp + (size_t)z * SD;
            }
            launch_gemm(4, NROW, 256, 0, A1, 1024, nullptr, 0, W, ldw, B, C, ND, 0);
        }
        agg_finish_kernel<<<NROW, 256>>>(agg_b, dec_w, dec_b, outp, P + (size_t)it * SD, it);
    }

    (void)in_sizes; (void)n_in; (void)out_size;
}

// round 3
// speedup vs baseline: 1.9583x; 1.9583x over previous
#include <cuda_runtime.h>
#include <cstdint>

// ---------------------------------------------------------------------------
// Problem constants: B=64, T=4, N=6, IMG=128, CIN=3, VE=64, D=256, P=4, R=8
// ---------------------------------------------------------------------------
#define NB 64
#define NT 4
#define NN 6
#define NBT 256            // B*T
#define NROI 1536          // B*T*N
#define NROW 384           // B*N
#define ND 256
#define SD (NROW*ND)
#define NROLL 8

// ---------------------------------------------------------------------------
// Device scratch (static: no allocation anywhere)
// ---------------------------------------------------------------------------
__device__ float g_f1[(size_t)NBT * 64 * 64 * 64];
__device__ float g_f2[(size_t)NBT * 64 * 32 * 32];
__device__ float g_pool [NROI * 1024];
__device__ float g_obj  [NROI * ND];
__device__ float g_emb1 [NROI * ND];
__device__ float g_emb2 [NROI * ND];
__device__ float g_sttmp[NROI * ND];
__device__ float g_O[4 * SD];
__device__ float g_P[8 * SD];
__device__ float g_selfd[4 * SD];
__device__ float g_u[4 * SD];
__device__ float g_v[4 * SD];
__device__ float g_t[4 * SD];
__device__ float g_a[4 * SD];
__device__ float g_cs[NROW * 1024];
__device__ float g_aggp[4 * SD];
__device__ float g_r[NROW];

// ---------------------------------------------------------------------------
__global__ void r_kernel(const float* __restrict__ rois) {
    int i = blockIdx.x * 128 + threadIdx.x;
    if (i >= NROW) return;
    int b = i / NN, n = i % NN;
    float s = 0.f;
    for (int t = 0; t < NT; ++t) {
        const float* ro = rois + (size_t)(((b * NT + t) * NN) + n) * 5;
        s += ((ro[4] - ro[2]) * 0.5f + (ro[3] - ro[1]) * 0.5f) * 0.5f;
    }
    g_r[i] = s * 0.25f;
}

// ---------------------------------------------------------------------------
// conv1: (256,3,128,128) -> relu -> (256,64,64,64), 3x3 s2 SAME (pad hi only)
// grid (16, 256): each block does 4 oy rows, weights loaded ONCE per block.
// block 256 = 16 oxt x 16 cot, micro 4co x 4ox, scalar FFMA.
// ---------------------------------------------------------------------------
__global__ void conv1_kernel(const float* __restrict__ x,
                             const float* __restrict__ w1,
                             const float* __restrict__ b1) {
    int bx = blockIdx.x, bt = blockIdx.y;
    __shared__ float ins[3 * 3 * 132];   // [ci][kh][132]
    __shared__ float ws[27 * 64];        // [off][co]
    __shared__ float bs[64];
    int tid = threadIdx.x;
    for (int i = tid; i < 1728; i += 256) {
        int co = i / 27, off = i % 27;
        ws[off * 64 + co] = w1[i];
    }
    if (tid < 64) bs[tid] = b1[tid];

    int oxt = tid & 15, cot = tid >> 4;
    int ox0 = oxt * 4, co0 = cot * 4;

    for (int oyi = 0; oyi < 4; ++oyi) {
        int oy = bx * 4 + oyi;
        __syncthreads();
        for (int i = tid; i < 3 * 3 * 132; i += 256) {
            int ci = i / 396, rem = i % 396, kh = rem / 132, ix = rem % 132;
            int iy = 2 * oy + kh;
            float v = 0.f;
            if (iy < 128 && ix < 128)
                v = x[(((size_t)bt * 3 + ci) * 128 + iy) * 128 + ix];
            ins[i] = v;
        }
        __syncthreads();

        float acc[4][4] = {};
#pragma unroll
        for (int ci = 0; ci < 3; ++ci)
#pragma unroll
            for (int kh = 0; kh < 3; ++kh) {
                const float* ip = &ins[(ci * 3 + kh) * 132 + ox0 * 2];
                float iv[9];
#pragma unroll
                for (int j = 0; j < 9; ++j) iv[j] = ip[j];
#pragma unroll
                for (int kw = 0; kw < 3; ++kw) {
                    float4 w = *(const float4*)&ws[(ci * 9 + kh * 3 + kw) * 64 + co0];
#pragma unroll
                    for (int dx = 0; dx < 4; ++dx) {
                        float v = iv[2 * dx + kw];
                        acc[0][dx] += w.x * v;
                        acc[1][dx] += w.y * v;
                        acc[2][dx] += w.z * v;
                        acc[3][dx] += w.w * v;
                    }
                }
            }
#pragma unroll
        for (int dc = 0; dc < 4; ++dc) {
            float bb = bs[co0 + dc];
            float4 o;
            o.x = fmaxf(acc[dc][0] + bb, 0.f);
            o.y = fmaxf(acc[dc][1] + bb, 0.f);
            o.z = fmaxf(acc[dc][2] + bb, 0.f);
            o.w = fmaxf(acc[dc][3] + bb, 0.f);
            *(float4*)&g_f1[(((size_t)bt * 64 + co0 + dc) * 64 + oy) * 64 + ox0] = o;
        }
    }
}

// ---------------------------------------------------------------------------
// conv2: (256,64,64,64) -> relu -> (256,64,32,32), 3x3 s2 SAME
// grid (16, 256): each block does 2 oy rows (5 shared input rows per ci chunk).
// block 128 = 4 oxt x 16 cot x 2 oyt; micro 4co x 8ox; ci chunks of 8.
// ---------------------------------------------------------------------------
__global__ void conv2_kernel(const float* __restrict__ w2,
                             const float* __restrict__ b2) {
    int bx = blockIdx.x, bt = blockIdx.y;
    __shared__ float ins[8 * 5 * 68];    // [ci][r(0..4)][68]
    __shared__ float ws[8 * 9 * 64];     // [off][co]
    int tid = threadIdx.x;
    int oxt = tid & 3, cot = (tid >> 2) & 15, oyt = tid >> 6;
    int ox0 = oxt * 8, co0 = cot * 4;
    int oy = bx * 2 + oyt;
    float acc[4][8] = {};
#pragma unroll 1
    for (int cc = 0; cc < 8; ++cc) {
        __syncthreads();
        for (int i = tid; i < 8 * 5 * 68; i += 128) {
            int ci = i / 340, rem = i % 340, r = rem / 68, ix = rem % 68;
            int iy = 4 * bx + r;
            int cig = cc * 8 + ci;
            float v = 0.f;
            if (ix < 64 && iy < 64)
                v = g_f1[(((size_t)bt * 64 + cig) * 64 + iy) * 64 + ix];
            ins[i] = v;
        }
        for (int i = tid; i < 64 * 72; i += 128) {
            int co = i / 72, off = i % 72;
            ws[off * 64 + co] = w2[(size_t)co * 576 + cc * 72 + off];
        }
        __syncthreads();
#pragma unroll
        for (int ci = 0; ci < 8; ++ci)
#pragma unroll
            for (int kh = 0; kh < 3; ++kh) {
                const float* ip = &ins[(ci * 5 + 2 * oyt + kh) * 68 + ox0 * 2];
                float iv[17];
#pragma unroll
                for (int q = 0; q < 4; ++q)
                    *(float4*)&iv[4 * q] = *(const float4*)&ip[4 * q];
                iv[16] = ip[16];
#pragma unroll
                for (int kw = 0; kw < 3; ++kw) {
                    float4 w = *(const float4*)&ws[((ci * 3 + kh) * 3 + kw) * 64 + co0];
#pragma unroll
                    for (int dx = 0; dx < 8; ++dx) {
                        float v = iv[2 * dx + kw];
                        acc[0][dx] += w.x * v;
                        acc[1][dx] += w.y * v;
                        acc[2][dx] += w.z * v;
                        acc[3][dx] += w.w * v;
                    }
                }
            }
    }
#pragma unroll
    for (int dc = 0; dc < 4; ++dc) {
        float bb = b2[co0 + dc];
        float* op = &g_f2[(((size_t)bt * 64 + co0 + dc) * 32 + oy) * 32 + ox0];
        float4 o0, o1;
        o0.x = fmaxf(acc[dc][0] + bb, 0.f); o0.y = fmaxf(acc[dc][1] + bb, 0.f);
        o0.z = fmaxf(acc[dc][2] + bb, 0.f); o0.w = fmaxf(acc[dc][3] + bb, 0.f);
        o1.x = fmaxf(acc[dc][4] + bb, 0.f); o1.y = fmaxf(acc[dc][5] + bb, 0.f);
        o1.z = fmaxf(acc[dc][6] + bb, 0.f); o1.w = fmaxf(acc[dc][7] + bb, 0.f);
        *(float4*)op = o0;
        *(float4*)(op + 4) = o1;
    }
}

// ---------------------------------------------------------------------------
__global__ void roi_kernel(const float* __restrict__ rois) {
    int r = blockIdx.x;
    __shared__ float ro[5];
    if (threadIdx.x < 5) ro[threadIdx.x] = rois[(size_t)r * 5 + threadIdx.x];
    __syncthreads();
    int bt = (int)ro[0];
    float x1 = ro[1] * 0.25f, y1 = ro[2] * 0.25f;
    float x2 = ro[3] * 0.25f, y2 = ro[4] * 0.25f;
    float bw = fmaxf(x2 - x1, 1.f) * 0.25f;
    float bh = fmaxf(y2 - y1, 1.f) * 0.25f;
    for (int idx = threadIdx.x; idx < 1024; idx += 256) {
        int c = idx >> 4, py = (idx >> 2) & 3, px = idx & 3;
        float sx = x1 + bw * (px + 0.5f);
        float sy = y1 + bh * (py + 0.5f);
        float x0f = fminf(fmaxf(floorf(sx), 0.f), 31.f);
        float y0f = fminf(fmaxf(floorf(sy), 0.f), 31.f);
        float lx = fminf(fmaxf(sx - x0f, 0.f), 1.f);
        float ly = fminf(fmaxf(sy - y0f, 0.f), 1.f);
        int x0 = (int)x0f, y0 = (int)y0f;
        int x1i = min(x0 + 1, 31), y1i = min(y0 + 1, 31);
        const float* f = &g_f2[((size_t)bt * 64 + c) * 1024];
        float v00 = f[y0 * 32 + x0];
        float v01 = f[y0 * 32 + x1i];
        float v10 = f[y1i * 32 + x0];
        float v11 = f[y1i * 32 + x1i];
        float val = v00 * (1.f - ly) * (1.f - lx) + v01 * (1.f - ly) * lx +
                    v10 * ly * (1.f - lx) + v11 * ly * lx;
        g_pool[(size_t)r * 1024 + idx] = val;
    }
}

// ---------------------------------------------------------------------------
__global__ void emb0_kernel(const float* __restrict__ sc,
                            const float* __restrict__ w,
                            const float* __restrict__ b) {
    int row = blockIdx.x, c = threadIdx.x;
    float x0 = sc[(size_t)row * 2], x1 = sc[(size_t)row * 2 + 1];
    float e = fmaf(w[c * 2], x0, fmaf(w[c * 2 + 1], x1, b[c]));
    g_emb1[(size_t)row * ND + c] = fmaxf(e, 0.f);
}

__global__ void rearr_kernel() {
    int i = blockIdx.x * 256 + threadIdx.x;
    int d = i & 255;
    int m = i >> 8;
    int n = m % NN;
    int t = (m / NN) % NT;
    int b = m / (NN * NT);
    g_O[((size_t)t * NROW + b * NN + n) * ND + d] = g_sttmp[i];
}

// ---------------------------------------------------------------------------
// Generic NT GEMM (round-1 proven): 64x64 tile, 256 threads, micro 4x4.
// C[m,n] = act( sum_k A(m,k) * W[n,k] + bias[n] ); A = concat(A1,A2) cols.
// ---------------------------------------------------------------------------
struct GemmArgs {
    const float* A1[12];
    const float* A2[12];
    const float* W[12];
    const float* Bias[12];
    float*       C[12];
    int          ldw[12];
    int lda1, lda2, ldc, K1, K2, relu;
};

__global__ void gemm_nt_kernel(GemmArgs g) {
    const int z = blockIdx.z;
    const float* __restrict__ A1 = g.A1[z];
    const float* __restrict__ A2 = g.A2[z];
    const float* __restrict__ W  = g.W[z];
    const float* __restrict__ Bv = g.Bias[z];
    float* __restrict__ C = g.C[z];
    const int ldw = g.ldw[z];
    const int m0 = blockIdx.x * 64, n0 = blockIdx.y * 64;
    __shared__ float As[16 * 68];
    __shared__ float Ws[16 * 68];
    const int tid = threadIdx.x;
    const int lr = tid >> 2, lc = (tid & 3) * 4;
    const int ty = tid >> 4, tx = tid & 15;
    float acc[4][4] = {};
    const int K = g.K1 + g.K2;
    for (int kk = 0; kk < K; kk += 16) {
        int col = kk + lc;
        const float* ap;
        if (col < g.K1) ap = A1 + (size_t)(m0 + lr) * g.lda1 + col;
        else            ap = A2 + (size_t)(m0 + lr) * g.lda2 + (col - g.K1);
        float4 av = *(const float4*)ap;
        float4 wv = *(const float4*)(W + (size_t)(n0 + lr) * ldw + col);
        As[(lc + 0) * 68 + lr] = av.x; As[(lc + 1) * 68 + lr] = av.y;
        As[(lc + 2) * 68 + lr] = av.z; As[(lc + 3) * 68 + lr] = av.w;
        Ws[(lc + 0) * 68 + lr] = wv.x; Ws[(lc + 1) * 68 + lr] = wv.y;
        Ws[(lc + 2) * 68 + lr] = wv.z; Ws[(lc + 3) * 68 + lr] = wv.w;
        __syncthreads();
#pragma unroll
        for (int k = 0; k < 16; ++k) {
            float4 a = *(const float4*)&As[k * 68 + ty * 4];
            float4 b = *(const float4*)&Ws[k * 68 + tx * 4];
            acc[0][0] += a.x * b.x; acc[0][1] += a.x * b.y; acc[0][2] += a.x * b.z; acc[0][3] += a.x * b.w;
            acc[1][0] += a.y * b.x; acc[1][1] += a.y * b.y; acc[1][2] += a.y * b.z; acc[1][3] += a.y * b.w;
            acc[2][0] += a.z * b.x; acc[2][1] += a.z * b.y; acc[2][2] += a.z * b.z; acc[2][3] += a.z * b.w;
            acc[3][0] += a.w * b.x; acc[3][1] += a.w * b.y; acc[3][2] += a.w * b.z; acc[3][3] += a.w * b.w;
        }
        __syncthreads();
    }
    int n = n0 + tx * 4;
    float b0 = 0.f, b1 = 0.f, b2 = 0.f, b3 = 0.f;
    if (Bv) { b0 = Bv[n]; b1 = Bv[n + 1]; b2 = Bv[n + 2]; b3 = Bv[n + 3]; }
#pragma unroll
    for (int i = 0; i < 4; ++i) {
        float4 o;
        o.x = acc[i][0] + b0; o.y = acc[i][1] + b1;
        o.z = acc[i][2] + b2; o.w = acc[i][3] + b3;
        if (g.relu) {
            o.x = fmaxf(o.x, 0.f); o.y = fmaxf(o.y, 0.f);
            o.z = fmaxf(o.z, 0.f); o.w = fmaxf(o.w, 0.f);
        }
        *(float4*)(C + (size_t)(m0 + ty * 4 + i) * g.ldc + n) = o;
    }
}

// ---------------------------------------------------------------------------
// masked relational sum
// ---------------------------------------------------------------------------
struct MaskArgs {
    const float* coor[4];
    int cbs[4];
    int cns[4];
    const float* relb;
};

__global__ void mask_relsum_kernel(MaskArgs ma) {
    int b = blockIdx.x, k = blockIdx.y;
    __shared__ float cx[NN], cy[NN], rr[NN], cnt[NN];
    __shared__ int   mask[NN][NN];
    int tid = threadIdx.x;
    if (tid < NN) {
        const float* cp = ma.coor[k] + (size_t)b * ma.cbs[k] + tid * ma.cns[k];
        cx[tid] = cp[0];
        cy[tid] = cp[1];
        rr[tid] = g_r[b * NN + tid];
    }
    __syncthreads();
    if (tid < NN * NN) {
        int i = tid / NN, j = tid % NN;
        float dx = cx[i] - cx[j], dy = cy[i] - cy[j];
        float dist = sqrtf(dx * dx + dy * dy);
        mask[i][j] = (i != j) && (dist <= rr[i] + rr[j]);
    }
    __syncthreads();
    if (tid < NN) {
        int c = 0;
        for (int j = 0; j < NN; ++j) c += mask[tid][j];
        cnt[tid] = (float)c;
    }
    __syncthreads();
    int d = tid;
    float rb = ma.relb[k * ND + d];
    size_t base = (size_t)k * SD + (size_t)b * NN * ND;
    float vv[NN];
#pragma unroll
    for (int j = 0; j < NN; ++j) vv[j] = g_v[base + j * ND + d];
#pragma unroll
    for (int i = 0; i < NN; ++i) {
        float acc = g_selfd[base + i * ND + d] + cnt[i] * (g_u[base + i * ND + d] + rb);
#pragma unroll
        for (int j = 0; j < NN; ++j)
            if (mask[i][j]) acc += vv[j];
        g_t[base + i * ND + d] = acc;
    }
}

// ---------------------------------------------------------------------------
// agg_finish: sum 4 split-K partials + bias -> s (state), then dec -> bbox.
// ---------------------------------------------------------------------------
__global__ void agg_finish_kernel(const float* __restrict__ aggb,
                                  const float* __restrict__ dw,
                                  const float* __restrict__ db,
                                  float* __restrict__ out,
                                  float* __restrict__ Pst, int it) {
    int row = blockIdx.x, tid = threadIdx.x;
    size_t off = (size_t)row * ND + tid;
    float s = aggb[tid] + g_aggp[off] + g_aggp[SD + off] +
              g_aggp[2 * SD + off] + g_aggp[3 * SD + off];
    Pst[off] = s;
    float p0 = s * dw[tid];
    float p1 = s * dw[256 + tid];
    float p2 = s * dw[512 + tid];
    float p3 = s * dw[768 + tid];
#pragma unroll
    for (int o = 16; o > 0; o >>= 1) {
        p0 += __shfl_down_sync(0xffffffffu, p0, o);
        p1 += __shfl_down_sync(0xffffffffu, p1, o);
        p2 += __shfl_down_sync(0xffffffffu, p2, o);
        p3 += __shfl_down_sync(0xffffffffu, p3, o);
    }
    __shared__ float sw[8][4];
    int wid = tid >> 5, lane = tid & 31;
    if (lane == 0) { sw[wid][0] = p0; sw[wid][1] = p1; sw[wid][2] = p2; sw[wid][3] = p3; }
    __syncthreads();
    if (tid < 4) {
        float acc = db[tid];
#pragma unroll
        for (int w = 0; w < 8; ++w) acc += sw[w][tid];
        int b = row / NN, n = row % NN;
        out[(size_t)b * (NROLL * NN * 4) + it * (NN * 4) + n * 4 + tid] = acc;
    }
}

// ---------------------------------------------------------------------------
// Host launcher
// ---------------------------------------------------------------------------
static void launch_gemm(int numZ, int M, int K1, int K2,
                        const float* const* A1, int lda1,
                        const float* const* A2, int lda2,
                        const float* const* W, const int* ldw,
                        const float* const* Bias,
                        float* const* C, int ldc, int relu) {
    GemmArgs ga;
    for (int z = 0; z < numZ; ++z) {
        ga.A1[z] = A1[z];
        ga.A2[z] = A2 ? A2[z] : A1[z];
        ga.W[z] = W[z];
        ga.Bias[z] = Bias ? Bias[z] : nullptr;
        ga.C[z] = C[z];
        ga.ldw[z] = ldw[z];
    }
    for (int z = numZ; z < 12; ++z) {
        ga.A1[z] = ga.A1[0]; ga.A2[z] = ga.A2[0]; ga.W[z] = ga.W[0];
        ga.Bias[z] = nullptr; ga.C[z] = ga.C[0]; ga.ldw[z] = ga.ldw[0];
    }
    ga.lda1 = lda1; ga.lda2 = lda2; ga.ldc = ldc;
    ga.K1 = K1; ga.K2 = K2; ga.relu = relu;
    dim3 grid(M / 64, 4, numZ);
    gemm_nt_kernel<<<grid, 256>>>(ga);
}

extern "C" void kernel_launch(void* const* d_in, const int* in_sizes, int n_in,
                              void* d_out, int out_size) {
    const float* x       = (const float*)d_in[0];
    const float* rois    = (const float*)d_in[1];
    const float* src     = (const float*)d_in[2];
    const float* w_conv1 = (const float*)d_in[3];
    const float* b_conv1 = (const float*)d_in[4];
    const float* w_conv2 = (const float*)d_in[5];
    const float* b_conv2 = (const float*)d_in[6];
    const float* fc0_w   = (const float*)d_in[7];
    const float* fc0_b   = (const float*)d_in[8];
    const float* fc0c_w  = (const float*)d_in[9];
    const float* fc0c_b  = (const float*)d_in[10];
    const float* fc1c_w  = (const float*)d_in[11];
    const float* fc1c_b  = (const float*)d_in[12];
    const float* red_w   = (const float*)d_in[13];
    const float* red_b   = (const float*)d_in[14];
    const float* g_self_w = (const float*)d_in[15];
    const float* g_self_b = (const float*)d_in[16];
    const float* g_rel_w  = (const float*)d_in[17];
    const float* g_rel_b  = (const float*)d_in[18];
    const float* g_aff_w  = (const float*)d_in[19];
    const float* g_aff_b  = (const float*)d_in[20];
    const float* g_out_w  = (const float*)d_in[21];
    const float* g_out_b  = (const float*)d_in[22];
    const float* agg_w   = (const float*)d_in[23];
    const float* agg_b   = (const float*)d_in[24];
    const float* dec_w   = (const float*)d_in[25];
    const float* dec_b   = (const float*)d_in[26];
    float* outp = (float*)d_out;

    float *pool, *obj, *emb1, *emb2, *sttmp, *O, *P, *selfd, *u, *v, *t, *a, *cs, *aggp;
    cudaGetSymbolAddress((void**)&pool,  g_pool);
    cudaGetSymbolAddress((void**)&obj,   g_obj);
    cudaGetSymbolAddress((void**)&emb1,  g_emb1);
    cudaGetSymbolAddress((void**)&emb2,  g_emb2);
    cudaGetSymbolAddress((void**)&sttmp, g_sttmp);
    cudaGetSymbolAddress((void**)&O,     g_O);
    cudaGetSymbolAddress((void**)&P,     g_P);
    cudaGetSymbolAddress((void**)&selfd, g_selfd);
    cudaGetSymbolAddress((void**)&u,     g_u);
    cudaGetSymbolAddress((void**)&v,     g_v);
    cudaGetSymbolAddress((void**)&t,     g_t);
    cudaGetSymbolAddress((void**)&a,     g_a);
    cudaGetSymbolAddress((void**)&cs,    g_cs);
    cudaGetSymbolAddress((void**)&aggp,  g_aggp);

    // ---- preamble ----
    r_kernel<<<3, 128>>>(rois);
    conv1_kernel<<<dim3(16, NBT), 256>>>(x, w_conv1, b_conv1);
    conv2_kernel<<<dim3(16, NBT), 128>>>(w_conv2, b_conv2);
    roi_kernel<<<NROI, 256>>>(rois);
    emb0_kernel<<<NROI, 256>>>(src, fc0c_w, fc0c_b);

    {   // fc1c
        const float* A1[1] = { emb1 };
        const float* W[1] = { fc1c_w }; int ldw[1] = { 256 };
        const float* B[1] = { fc1c_b };
        float* C[1] = { emb2 };
        launch_gemm(1, NROI, 256, 0, A1, 256, nullptr, 0, W, ldw, B, C, ND, 1);
    }
    {   // fc0
        const float* A1[1] = { pool };
        const float* W[1] = { fc0_w }; int ldw[1] = { 1024 };
        const float* B[1] = { fc0_b };
        float* C[1] = { obj };
        launch_gemm(1, NROI, 1024, 0, A1, 1024, nullptr, 0, W, ldw, B, C, ND, 1);
    }
    {   // red
        const float* A1[1] = { obj };
        const float* A2[1] = { emb2 };
        const float* W[1] = { red_w }; int ldw[1] = { 512 };
        const float* B[1] = { red_b };
        float* C[1] = { sttmp };
        launch_gemm(1, NROI, 256, 256, A1, 256, A2, 256, W, ldw, B, C, ND, 1);
    }
    rearr_kernel<<<NROI, 256>>>();

    // ---- rollouts ----
    for (int it = 0; it < NROLL; ++it) {
        const float* st[4];
        MaskArgs ma;
        for (int k = 0; k < 4; ++k) {
            int idx = it + k;
            st[k] = (idx < 4) ? (O + (size_t)idx * SD) : (P + (size_t)(idx - 4) * SD);
            if (idx < 4) {
                ma.coor[k] = src + idx * (NN * 2);
                ma.cbs[k] = NT * NN * 2;
                ma.cns[k] = 2;
            } else {
                ma.coor[k] = outp + (idx - 4) * (NN * 4) + 2;
                ma.cbs[k] = NROLL * NN * 4;
                ma.cns[k] = 4;
            }
        }
        ma.relb = g_rel_b;

        {   // selfd / u / v : 12-way batched GEMM
            const float* A1[12]; const float* W[12]; const float* B[12];
            float* C[12]; int ldw[12];
            for (int z = 0; z < 12; ++z) {
                int k = z & 3, kind = z >> 2;
                A1[z] = st[k];
                if (kind == 0)      { W[z] = g_self_w + (size_t)k * 65536;       ldw[z] = 256; B[z] = g_self_b + k * 256; C[z] = selfd + (size_t)k * SD; }
                else if (kind == 1) { W[z] = g_rel_w + (size_t)k * 131072;       ldw[z] = 512; B[z] = nullptr;            C[z] = u + (size_t)k * SD; }
                else                { W[z] = g_rel_w + (size_t)k * 131072 + 256; ldw[z] = 512; B[z] = nullptr;            C[z] = v + (size_t)k * SD; }
            }
            launch_gemm(12, NROW, 256, 0, A1, 256, nullptr, 0, W, ldw, B, C, ND, 0);
        }
        mask_relsum_kernel<<<dim3(NB, 4), 256>>>(ma);
        {   // aff
            const float* A1[4]; const float* W[4]; const float* B[4];
            float* C[4]; int ldw[4];
            for (int k = 0; k < 4; ++k) {
                A1[k] = t + (size_t)k * SD;
                W[k] = g_aff_w + (size_t)k * 65536; ldw[k] = 256;
                B[k] = g_aff_b + k * 256;
                C[k] = a + (size_t)k * SD;
            }
            launch_gemm(4, NROW, 256, 0, A1, 256, nullptr, 0, W, ldw, B, C, ND, 1);
        }
        {   // out: cs_k = relu(concat(a, state) @ ow.T + b)
            const float* A1[4]; const float* A2[4]; const float* W[4]; const float* B[4];
            float* C[4]; int ldw[4];
            for (int k = 0; k < 4; ++k) {
                A1[k] = a + (size_t)k * SD;
                A2[k] = st[k];
                W[k] = g_out_w + (size_t)k * 131072; ldw[k] = 512;
                B[k] = g_out_b + k * 256;
                C[k] = cs + k * 256;
            }
            launch_gemm(4, NROW, 256, 256, A1, 256, A2, 256, W, ldw, B, C, 1024, 1);
        }
        {   // agg split-K x4 -> partials
            const float* A1[4]; const float* W[4]; const float* B[4];
            float* C[4]; int ldw[4];
            for (int z = 0; z < 4; ++z) {
                A1[z] = cs + z * 256;
                W[z] = agg_w + z * 256; ldw[z] = 1024;
                B[z] = nullptr;
                C[z] = aggp + (size_t)z * SD;
            }
            launch_gemm(4, NROW, 256, 0, A1, 1024, nullptr, 0, W, ldw, B, C, ND, 0);
        }
        agg_finish_kernel<<<NROW, 256>>>(agg_b, dec_w, dec_b, outp, P + (size_t)it * SD, it);
    }

    (void)in_sizes; (void)n_in; (void)out_size;
}

// round 4
// speedup vs baseline: 2.6605x; 1.3586x over previous
#include <cuda_runtime.h>
#include <cuda_bf16.h>
#include <cstdint>

// ---------------------------------------------------------------------------
// Problem constants: B=64, T=4, N=6, IMG=128, CIN=3, VE=64, D=256, P=4, R=8
// ---------------------------------------------------------------------------
#define NB 64
#define NT 4
#define NN 6
#define NBT 256            // B*T
#define NROI 1536          // B*T*N
#define NROW 384           // B*N
#define ND 256
#define SD (NROW*ND)
#define NROLL 8

// ---------------------------------------------------------------------------
// Device scratch (static: no allocation anywhere)
// ---------------------------------------------------------------------------
__device__ float g_f1[(size_t)NBT * 64 * 64 * 64];
__device__ float g_f2[(size_t)NBT * 64 * 32 * 32];
__device__ float g_pool [NROI * 1024];
__device__ float g_obj  [NROI * ND];
__device__ float g_emb1 [NROI * ND];
__device__ float g_emb2 [NROI * ND];
__device__ float g_sttmp[NROI * ND];
__device__ float g_O[4 * SD];
__device__ float g_P[8 * SD];
__device__ float g_selfd[4 * SD];
__device__ float g_u[4 * SD];
__device__ float g_v[4 * SD];
__device__ float g_t[4 * SD];
__device__ float g_a[4 * SD];
__device__ float g_cs[NROW * 1024];
__device__ float g_aggp[4 * SD];
__device__ float g_r[NROW];

// ---------------------------------------------------------------------------
__global__ void r_kernel(const float* __restrict__ rois) {
    int i = blockIdx.x * 128 + threadIdx.x;
    if (i >= NROW) return;
    int b = i / NN, n = i % NN;
    float s = 0.f;
    for (int t = 0; t < NT; ++t) {
        const float* ro = rois + (size_t)(((b * NT + t) * NN) + n) * 5;
        s += ((ro[4] - ro[2]) * 0.5f + (ro[3] - ro[1]) * 0.5f) * 0.5f;
    }
    g_r[i] = s * 0.25f;
}

// ---------------------------------------------------------------------------
// conv1: (256,3,128,128) -> relu -> (256,64,64,64), 3x3 s2 SAME (pad hi only)
// grid (16, 256): each block does 4 oy rows, weights loaded ONCE per block.
// ---------------------------------------------------------------------------
__global__ void conv1_kernel(const float* __restrict__ x,
                             const float* __restrict__ w1,
                             const float* __restrict__ b1) {
    int bx = blockIdx.x, bt = blockIdx.y;
    __shared__ float ins[3 * 3 * 132];
    __shared__ float ws[27 * 64];
    __shared__ float bs[64];
    int tid = threadIdx.x;
    for (int i = tid; i < 1728; i += 256) {
        int co = i / 27, off = i % 27;
        ws[off * 64 + co] = w1[i];
    }
    if (tid < 64) bs[tid] = b1[tid];

    int oxt = tid & 15, cot = tid >> 4;
    int ox0 = oxt * 4, co0 = cot * 4;

    for (int oyi = 0; oyi < 4; ++oyi) {
        int oy = bx * 4 + oyi;
        __syncthreads();
        for (int i = tid; i < 3 * 3 * 132; i += 256) {
            int ci = i / 396, rem = i % 396, kh = rem / 132, ix = rem % 132;
            int iy = 2 * oy + kh;
            float v = 0.f;
            if (iy < 128 && ix < 128)
                v = x[(((size_t)bt * 3 + ci) * 128 + iy) * 128 + ix];
            ins[i] = v;
        }
        __syncthreads();

        float acc[4][4] = {};
#pragma unroll
        for (int ci = 0; ci < 3; ++ci)
#pragma unroll
            for (int kh = 0; kh < 3; ++kh) {
                const float* ip = &ins[(ci * 3 + kh) * 132 + ox0 * 2];
                float iv[9];
#pragma unroll
                for (int j = 0; j < 9; ++j) iv[j] = ip[j];
#pragma unroll
                for (int kw = 0; kw < 3; ++kw) {
                    float4 w = *(const float4*)&ws[(ci * 9 + kh * 3 + kw) * 64 + co0];
#pragma unroll
                    for (int dx = 0; dx < 4; ++dx) {
                        float v = iv[2 * dx + kw];
                        acc[0][dx] += w.x * v;
                        acc[1][dx] += w.y * v;
                        acc[2][dx] += w.z * v;
                        acc[3][dx] += w.w * v;
                    }
                }
            }
#pragma unroll
        for (int dc = 0; dc < 4; ++dc) {
            float bb = bs[co0 + dc];
            float4 o;
            o.x = fmaxf(acc[dc][0] + bb, 0.f);
            o.y = fmaxf(acc[dc][1] + bb, 0.f);
            o.z = fmaxf(acc[dc][2] + bb, 0.f);
            o.w = fmaxf(acc[dc][3] + bb, 0.f);
            *(float4*)&g_f1[(((size_t)bt * 64 + co0 + dc) * 64 + oy) * 64 + ox0] = o;
        }
    }
}

// ---------------------------------------------------------------------------
// conv2 via tensor cores: implicit GEMM, mma.sync.m16n8k16 bf16, 2-term split.
// CTA = (oy block of 4 rows = 128 px, one bt image), 256 threads (8 warps).
// M=128 px (warp w owns rows 16w..16w+15), N=64 co, K = 9 taps x 64 ci
// processed as 18 chunks of 32 ci. D = Ah*Bh + Ah*Bl + Al*Bh (fp32 accum).
// smem row stride 40 bf16 -> conflict-free fragment loads.
// ---------------------------------------------------------------------------
#define MMA_BF16(d, a0, a1, a2, a3, b0, b1)                                    \
    asm volatile(                                                              \
        "mma.sync.aligned.m16n8k16.row.col.f32.bf16.bf16.f32 "                \
        "{%0,%1,%2,%3},{%4,%5,%6,%7},{%8,%9},{%0,%1,%2,%3};"                  \
        : "+f"(d[0]), "+f"(d[1]), "+f"(d[2]), "+f"(d[3])                       \
        : "r"(a0), "r"(a1), "r"(a2), "r"(a3), "r"(b0), "r"(b1))

__global__ void conv2_mma_kernel(const float* __restrict__ w2,
                                 const float* __restrict__ b2) {
    __shared__ __nv_bfloat16 Ah[128 * 40];
    __shared__ __nv_bfloat16 Al[128 * 40];
    __shared__ __nv_bfloat16 Bh[64 * 40];
    __shared__ __nv_bfloat16 Bl[64 * 40];

    int tid = threadIdx.x;
    int w = tid >> 5, lane = tid & 31;
    int g = lane >> 2, tq = lane & 3;
    int bx = blockIdx.x, bt = blockIdx.y;
    const float* f1p = &g_f1[(size_t)bt * 64 * 4096];

    float d[8][4] = {};

#pragma unroll 1
    for (int tap = 0; tap < 9; ++tap) {
        int kh = tap / 3, kw = tap % 3;
#pragma unroll 1
        for (int half = 0; half < 2; ++half) {
            int cb = half * 32;
            __syncthreads();
            // Build A tile: 128 px x 32 ci (hi/lo bf16)
            for (int idx = tid; idx < 4096; idx += 256) {
                int m = idx & 127, kk = idx >> 7;
                int dy = m >> 5, ox = m & 31;
                int iy = 2 * (bx * 4 + dy) + kh;
                int ix = 2 * ox + kw;
                float v = 0.f;
                if (iy < 64 && ix < 64)
                    v = f1p[(size_t)(cb + kk) * 4096 + iy * 64 + ix];
                __nv_bfloat16 hi = __float2bfloat16(v);
                float lo = v - __bfloat162float(hi);
                Ah[m * 40 + kk] = hi;
                Al[m * 40 + kk] = __float2bfloat16(lo);
            }
            // Build B tile: 64 co x 32 ci
            for (int idx = tid; idx < 2048; idx += 256) {
                int n = idx >> 5, kk = idx & 31;
                float v = w2[(size_t)n * 576 + (cb + kk) * 9 + tap];
                __nv_bfloat16 hi = __float2bfloat16(v);
                float lo = v - __bfloat162float(hi);
                Bh[n * 40 + kk] = hi;
                Bl[n * 40 + kk] = __float2bfloat16(lo);
            }
            __syncthreads();
#pragma unroll
            for (int ks = 0; ks < 2; ++ks) {
                int k0 = ks * 16 + tq * 2;
                int r0 = w * 16 + g;
                uint32_t ah0 = *(const uint32_t*)&Ah[r0 * 40 + k0];
                uint32_t ah1 = *(const uint32_t*)&Ah[(r0 + 8) * 40 + k0];
                uint32_t ah2 = *(const uint32_t*)&Ah[r0 * 40 + k0 + 8];
                uint32_t ah3 = *(const uint32_t*)&Ah[(r0 + 8) * 40 + k0 + 8];
                uint32_t al0 = *(const uint32_t*)&Al[r0 * 40 + k0];
                uint32_t al1 = *(const uint32_t*)&Al[(r0 + 8) * 40 + k0];
                uint32_t al2 = *(const uint32_t*)&Al[r0 * 40 + k0 + 8];
                uint32_t al3 = *(const uint32_t*)&Al[(r0 + 8) * 40 + k0 + 8];
#pragma unroll
                for (int nt = 0; nt < 8; ++nt) {
                    int nr = nt * 8 + g;
                    uint32_t bh0 = *(const uint32_t*)&Bh[nr * 40 + k0];
                    uint32_t bh1 = *(const uint32_t*)&Bh[nr * 40 + k0 + 8];
                    uint32_t bl0 = *(const uint32_t*)&Bl[nr * 40 + k0];
                    uint32_t bl1 = *(const uint32_t*)&Bl[nr * 40 + k0 + 8];
                    MMA_BF16(d[nt], ah0, ah1, ah2, ah3, bh0, bh1);
                    MMA_BF16(d[nt], ah0, ah1, ah2, ah3, bl0, bl1);
                    MMA_BF16(d[nt], al0, al1, al2, al3, bh0, bh1);
                }
            }
        }
    }

    // Epilogue: bias + relu, scatter to g_f2[bt][co][oy][ox]
    int oyb = bx * 4;
#pragma unroll
    for (int nt = 0; nt < 8; ++nt) {
        int co = nt * 8 + tq * 2;     // C col = (lane%4)*2
        int px = w * 16 + g;          // C row = lane>>2
        float bias0 = b2[co], bias1 = b2[co + 1];
#pragma unroll
        for (int h = 0; h < 2; ++h) { // h=0: rows px, h=1: rows px+8
            int p = px + h * 8;
            int dy = p >> 5, ox = p & 31;
            size_t base = (((size_t)bt * 64 + co) * 32 + oyb + dy) * 32 + ox;
            g_f2[base]        = fmaxf(d[nt][2 * h + 0] + bias0, 0.f);
            g_f2[base + 1024] = fmaxf(d[nt][2 * h + 1] + bias1, 0.f);
        }
    }
}

// ---------------------------------------------------------------------------
__global__ void roi_kernel(const float* __restrict__ rois) {
    int r = blockIdx.x;
    __shared__ float ro[5];
    if (threadIdx.x < 5) ro[threadIdx.x] = rois[(size_t)r * 5 + threadIdx.x];
    __syncthreads();
    int bt = (int)ro[0];
    float x1 = ro[1] * 0.25f, y1 = ro[2] * 0.25f;
    float x2 = ro[3] * 0.25f, y2 = ro[4] * 0.25f;
    float bw = fmaxf(x2 - x1, 1.f) * 0.25f;
    float bh = fmaxf(y2 - y1, 1.f) * 0.25f;
    for (int idx = threadIdx.x; idx < 1024; idx += 256) {
        int c = idx >> 4, py = (idx >> 2) & 3, px = idx & 3;
        float sx = x1 + bw * (px + 0.5f);
        float sy = y1 + bh * (py + 0.5f);
        float x0f = fminf(fmaxf(floorf(sx), 0.f), 31.f);
        float y0f = fminf(fmaxf(floorf(sy), 0.f), 31.f);
        float lx = fminf(fmaxf(sx - x0f, 0.f), 1.f);
        float ly = fminf(fmaxf(sy - y0f, 0.f), 1.f);
        int x0 = (int)x0f, y0 = (int)y0f;
        int x1i = min(x0 + 1, 31), y1i = min(y0 + 1, 31);
        const float* f = &g_f2[((size_t)bt * 64 + c) * 1024];
        float v00 = f[y0 * 32 + x0];
        float v01 = f[y0 * 32 + x1i];
        float v10 = f[y1i * 32 + x0];
        float v11 = f[y1i * 32 + x1i];
        float val = v00 * (1.f - ly) * (1.f - lx) + v01 * (1.f - ly) * lx +
                    v10 * ly * (1.f - lx) + v11 * ly * lx;
        g_pool[(size_t)r * 1024 + idx] = val;
    }
}

// ---------------------------------------------------------------------------
__global__ void emb0_kernel(const float* __restrict__ sc,
                            const float* __restrict__ w,
                            const float* __restrict__ b) {
    int row = blockIdx.x, c = threadIdx.x;
    float x0 = sc[(size_t)row * 2], x1 = sc[(size_t)row * 2 + 1];
    float e = fmaf(w[c * 2], x0, fmaf(w[c * 2 + 1], x1, b[c]));
    g_emb1[(size_t)row * ND + c] = fmaxf(e, 0.f);
}

__global__ void rearr_kernel() {
    int i = blockIdx.x * 256 + threadIdx.x;
    int d = i & 255;
    int m = i >> 8;
    int n = m % NN;
    int t = (m / NN) % NT;
    int b = m / (NN * NT);
    g_O[((size_t)t * NROW + b * NN + n) * ND + d] = g_sttmp[i];
}

// ---------------------------------------------------------------------------
// Generic NT GEMM: 64x64 tile, 256 threads, micro 4x4 (round-1 proven).
// ---------------------------------------------------------------------------
struct GemmArgs {
    const float* A1[12];
    const float* A2[12];
    const float* W[12];
    const float* Bias[12];
    float*       C[12];
    int          ldw[12];
    int lda1, lda2, ldc, K1, K2, relu;
};

__global__ void gemm_nt_kernel(GemmArgs g) {
    const int z = blockIdx.z;
    const float* __restrict__ A1 = g.A1[z];
    const float* __restrict__ A2 = g.A2[z];
    const float* __restrict__ W  = g.W[z];
    const float* __restrict__ Bv = g.Bias[z];
    float* __restrict__ C = g.C[z];
    const int ldw = g.ldw[z];
    const int m0 = blockIdx.x * 64, n0 = blockIdx.y * 64;
    __shared__ float As[16 * 68];
    __shared__ float Ws[16 * 68];
    const int tid = threadIdx.x;
    const int lr = tid >> 2, lc = (tid & 3) * 4;
    const int ty = tid >> 4, tx = tid & 15;
    float acc[4][4] = {};
    const int K = g.K1 + g.K2;
    for (int kk = 0; kk < K; kk += 16) {
        int col = kk + lc;
        const float* ap;
        if (col < g.K1) ap = A1 + (size_t)(m0 + lr) * g.lda1 + col;
        else            ap = A2 + (size_t)(m0 + lr) * g.lda2 + (col - g.K1);
        float4 av = *(const float4*)ap;
        float4 wv = *(const float4*)(W + (size_t)(n0 + lr) * ldw + col);
        As[(lc + 0) * 68 + lr] = av.x; As[(lc + 1) * 68 + lr] = av.y;
        As[(lc + 2) * 68 + lr] = av.z; As[(lc + 3) * 68 + lr] = av.w;
        Ws[(lc + 0) * 68 + lr] = wv.x; Ws[(lc + 1) * 68 + lr] = wv.y;
        Ws[(lc + 2) * 68 + lr] = wv.z; Ws[(lc + 3) * 68 + lr] = wv.w;
        __syncthreads();
#pragma unroll
        for (int k = 0; k < 16; ++k) {
            float4 a = *(const float4*)&As[k * 68 + ty * 4];
            float4 b = *(const float4*)&Ws[k * 68 + tx * 4];
            acc[0][0] += a.x * b.x; acc[0][1] += a.x * b.y; acc[0][2] += a.x * b.z; acc[0][3] += a.x * b.w;
            acc[1][0] += a.y * b.x; acc[1][1] += a.y * b.y; acc[1][2] += a.y * b.z; acc[1][3] += a.y * b.w;
            acc[2][0] += a.z * b.x; acc[2][1] += a.z * b.y; acc[2][2] += a.z * b.z; acc[2][3] += a.z * b.w;
            acc[3][0] += a.w * b.x; acc[3][1] += a.w * b.y; acc[3][2] += a.w * b.z; acc[3][3] += a.w * b.w;
        }
        __syncthreads();
    }
    int n = n0 + tx * 4;
    float b0 = 0.f, b1 = 0.f, b2 = 0.f, b3 = 0.f;
    if (Bv) { b0 = Bv[n]; b1 = Bv[n + 1]; b2 = Bv[n + 2]; b3 = Bv[n + 3]; }
#pragma unroll
    for (int i = 0; i < 4; ++i) {
        float4 o;
        o.x = acc[i][0] + b0; o.y = acc[i][1] + b1;
        o.z = acc[i][2] + b2; o.w = acc[i][3] + b3;
        if (g.relu) {
            o.x = fmaxf(o.x, 0.f); o.y = fmaxf(o.y, 0.f);
            o.z = fmaxf(o.z, 0.f); o.w = fmaxf(o.w, 0.f);
        }
        *(float4*)(C + (size_t)(m0 + ty * 4 + i) * g.ldc + n) = o;
    }
}

// ---------------------------------------------------------------------------
// masked relational sum
// ---------------------------------------------------------------------------
struct MaskArgs {
    const float* coor[4];
    int cbs[4];
    int cns[4];
    const float* relb;
};

__global__ void mask_relsum_kernel(MaskArgs ma) {
    int b = blockIdx.x, k = blockIdx.y;
    __shared__ float cx[NN], cy[NN], rr[NN], cnt[NN];
    __shared__ int   mask[NN][NN];
    int tid = threadIdx.x;
    if (tid < NN) {
        const float* cp = ma.coor[k] + (size_t)b * ma.cbs[k] + tid * ma.cns[k];
        cx[tid] = cp[0];
        cy[tid] = cp[1];
        rr[tid] = g_r[b * NN + tid];
    }
    __syncthreads();
    if (tid < NN * NN) {
        int i = tid / NN, j = tid % NN;
        float dx = cx[i] - cx[j], dy = cy[i] - cy[j];
        float dist = sqrtf(dx * dx + dy * dy);
        mask[i][j] = (i != j) && (dist <= rr[i] + rr[j]);
    }
    __syncthreads();
    if (tid < NN) {
        int c = 0;
        for (int j = 0; j < NN; ++j) c += mask[tid][j];
        cnt[tid] = (float)c;
    }
    __syncthreads();
    int d = tid;
    float rb = ma.relb[k * ND + d];
    size_t base = (size_t)k * SD + (size_t)b * NN * ND;
    float vv[NN];
#pragma unroll
    for (int j = 0; j < NN; ++j) vv[j] = g_v[base + j * ND + d];
#pragma unroll
    for (int i = 0; i < NN; ++i) {
        float acc = g_selfd[base + i * ND + d] + cnt[i] * (g_u[base + i * ND + d] + rb);
#pragma unroll
        for (int j = 0; j < NN; ++j)
            if (mask[i][j]) acc += vv[j];
        g_t[base + i * ND + d] = acc;
    }
}

// ---------------------------------------------------------------------------
// agg_finish: sum 4 split-K partials + bias -> state, then dec -> bbox.
// ---------------------------------------------------------------------------
__global__ void agg_finish_kernel(const float* __restrict__ aggb,
                                  const float* __restrict__ dw,
                                  const float* __restrict__ db,
                                  float* __restrict__ out,
                                  float* __restrict__ Pst, int it) {
    int row = blockIdx.x, tid = threadIdx.x;
    size_t off = (size_t)row * ND + tid;
    float s = aggb[tid] + g_aggp[off] + g_aggp[SD + off] +
              g_aggp[2 * SD + off] + g_aggp[3 * SD + off];
    Pst[off] = s;
    float p0 = s * dw[tid];
    float p1 = s * dw[256 + tid];
    float p2 = s * dw[512 + tid];
    float p3 = s * dw[768 + tid];
#pragma unroll
    for (int o = 16; o > 0; o >>= 1) {
        p0 += __shfl_down_sync(0xffffffffu, p0, o);
        p1 += __shfl_down_sync(0xffffffffu, p1, o);
        p2 += __shfl_down_sync(0xffffffffu, p2, o);
        p3 += __shfl_down_sync(0xffffffffu, p3, o);
    }
    __shared__ float sw[8][4];
    int wid = tid >> 5, lane = tid & 31;
    if (lane == 0) { sw[wid][0] = p0; sw[wid][1] = p1; sw[wid][2] = p2; sw[wid][3] = p3; }
    __syncthreads();
    if (tid < 4) {
        float acc = db[tid];
#pragma unroll
        for (int w = 0; w < 8; ++w) acc += sw[w][tid];
        int b = row / NN, n = row % NN;
        out[(size_t)b * (NROLL * NN * 4) + it * (NN * 4) + n * 4 + tid] = acc;
    }
}

// ---------------------------------------------------------------------------
// Host launcher
// ---------------------------------------------------------------------------
static void launch_gemm(int numZ, int M, int K1, int K2,
                        const float* const* A1, int lda1,
                        const float* const* A2, int lda2,
                        const float* const* W, const int* ldw,
                        const float* const* Bias,
                        float* const* C, int ldc, int relu) {
    GemmArgs ga;
    for (int z = 0; z < numZ; ++z) {
        ga.A1[z] = A1[z];
        ga.A2[z] = A2 ? A2[z] : A1[z];
        ga.W[z] = W[z];
        ga.Bias[z] = Bias ? Bias[z] : nullptr;
        ga.C[z] = C[z];
        ga.ldw[z] = ldw[z];
    }
    for (int z = numZ; z < 12; ++z) {
        ga.A1[z] = ga.A1[0]; ga.A2[z] = ga.A2[0]; ga.W[z] = ga.W[0];
        ga.Bias[z] = nullptr; ga.C[z] = ga.C[0]; ga.ldw[z] = ga.ldw[0];
    }
    ga.lda1 = lda1; ga.lda2 = lda2; ga.ldc = ldc;
    ga.K1 = K1; ga.K2 = K2; ga.relu = relu;
    dim3 grid(M / 64, 4, numZ);
    gemm_nt_kernel<<<grid, 256>>>(ga);
}

extern "C" void kernel_launch(void* const* d_in, const int* in_sizes, int n_in,
                              void* d_out, int out_size) {
    const float* x       = (const float*)d_in[0];
    const float* rois    = (const float*)d_in[1];
    const float* src     = (const float*)d_in[2];
    const float* w_conv1 = (const float*)d_in[3];
    const float* b_conv1 = (const float*)d_in[4];
    const float* w_conv2 = (const float*)d_in[5];
    const float* b_conv2 = (const float*)d_in[6];
    const float* fc0_w   = (const float*)d_in[7];
    const float* fc0_b   = (const float*)d_in[8];
    const float* fc0c_w  = (const float*)d_in[9];
    const float* fc0c_b  = (const float*)d_in[10];
    const float* fc1c_w  = (const float*)d_in[11];
    const float* fc1c_b  = (const float*)d_in[12];
    const float* red_w   = (const float*)d_in[13];
    const float* red_b   = (const float*)d_in[14];
    const float* g_self_w = (const float*)d_in[15];
    const float* g_self_b = (const float*)d_in[16];
    const float* g_rel_w  = (const float*)d_in[17];
    const float* g_rel_b  = (const float*)d_in[18];
    const float* g_aff_w  = (const float*)d_in[19];
    const float* g_aff_b  = (const float*)d_in[20];
    const float* g_out_w  = (const float*)d_in[21];
    const float* g_out_b  = (const float*)d_in[22];
    const float* agg_w   = (const float*)d_in[23];
    const float* agg_b   = (const float*)d_in[24];
    const float* dec_w   = (const float*)d_in[25];
    const float* dec_b   = (const float*)d_in[26];
    float* outp = (float*)d_out;

    float *pool, *obj, *emb1, *emb2, *sttmp, *O, *P, *selfd, *u, *v, *t, *a, *cs, *aggp;
    cudaGetSymbolAddress((void**)&pool,  g_pool);
    cudaGetSymbolAddress((void**)&obj,   g_obj);
    cudaGetSymbolAddress((void**)&emb1,  g_emb1);
    cudaGetSymbolAddress((void**)&emb2,  g_emb2);
    cudaGetSymbolAddress((void**)&sttmp, g_sttmp);
    cudaGetSymbolAddress((void**)&O,     g_O);
    cudaGetSymbolAddress((void**)&P,     g_P);
    cudaGetSymbolAddress((void**)&selfd, g_selfd);
    cudaGetSymbolAddress((void**)&u,     g_u);
    cudaGetSymbolAddress((void**)&v,     g_v);
    cudaGetSymbolAddress((void**)&t,     g_t);
    cudaGetSymbolAddress((void**)&a,     g_a);
    cudaGetSymbolAddress((void**)&cs,    g_cs);
    cudaGetSymbolAddress((void**)&aggp,  g_aggp);

    // ---- preamble ----
    r_kernel<<<3, 128>>>(rois);
    conv1_kernel<<<dim3(16, NBT), 256>>>(x, w_conv1, b_conv1);
    conv2_mma_kernel<<<dim3(8, NBT), 256>>>(w_conv2, b_conv2);
    roi_kernel<<<NROI, 256>>>(rois);
    emb0_kernel<<<NROI, 256>>>(src, fc0c_w, fc0c_b);

    {   // fc1c
        const float* A1[1] = { emb1 };
        const float* W[1] = { fc1c_w }; int ldw[1] = { 256 };
        const float* B[1] = { fc1c_b };
        float* C[1] = { emb2 };
        launch_gemm(1, NROI, 256, 0, A1, 256, nullptr, 0, W, ldw, B, C, ND, 1);
    }
    {   // fc0
        const float* A1[1] = { pool };
        const float* W[1] = { fc0_w }; int ldw[1] = { 1024 };
        const float* B[1] = { fc0_b };
        float* C[1] = { obj };
        launch_gemm(1, NROI, 1024, 0, A1, 1024, nullptr, 0, W, ldw, B, C, ND, 1);
    }
    {   // red
        const float* A1[1] = { obj };
        const float* A2[1] = { emb2 };
        const float* W[1] = { red_w }; int ldw[1] = { 512 };
        const float* B[1] = { red_b };
        float* C[1] = { sttmp };
        launch_gemm(1, NROI, 256, 256, A1, 256, A2, 256, W, ldw, B, C, ND, 1);
    }
    rearr_kernel<<<NROI, 256>>>();

    // ---- rollouts ----
    for (int it = 0; it < NROLL; ++it) {
        const float* st[4];
        MaskArgs ma;
        for (int k = 0; k < 4; ++k) {
            int idx = it + k;
            st[k] = (idx < 4) ? (O + (size_t)idx * SD) : (P + (size_t)(idx - 4) * SD);
            if (idx < 4) {
                ma.coor[k] = src + idx * (NN * 2);
                ma.cbs[k] = NT * NN * 2;
                ma.cns[k] = 2;
            } else {
                ma.coor[k] = outp + (idx - 4) * (NN * 4) + 2;
                ma.cbs[k] = NROLL * NN * 4;
                ma.cns[k] = 4;
            }
        }
        ma.relb = g_rel_b;

        {   // selfd / u / v : 12-way batched GEMM
            const float* A1[12]; const float* W[12]; const float* B[12];
            float* C[12]; int ldw[12];
            for (int z = 0; z < 12; ++z) {
                int k = z & 3, kind = z >> 2;
                A1[z] = st[k];
                if (kind == 0)      { W[z] = g_self_w + (size_t)k * 65536;       ldw[z] = 256; B[z] = g_self_b + k * 256; C[z] = selfd + (size_t)k * SD; }
                else if (kind == 1) { W[z] = g_rel_w + (size_t)k * 131072;       ldw[z] = 512; B[z] = nullptr;            C[z] = u + (size_t)k * SD; }
                else                { W[z] = g_rel_w + (size_t)k * 131072 + 256; ldw[z] = 512; B[z] = nullptr;            C[z] = v + (size_t)k * SD; }
            }
            launch_gemm(12, NROW, 256, 0, A1, 256, nullptr, 0, W, ldw, B, C, ND, 0);
        }
        mask_relsum_kernel<<<dim3(NB, 4), 256>>>(ma);
        {   // aff
            const float* A1[4]; const float* W[4]; const float* B[4];
            float* C[4]; int ldw[4];
            for (int k = 0; k < 4; ++k) {
                A1[k] = t + (size_t)k * SD;
                W[k] = g_aff_w + (size_t)k * 65536; ldw[k] = 256;
                B[k] = g_aff_b + k * 256;
                C[k] = a + (size_t)k * SD;
            }
            launch_gemm(4, NROW, 256, 0, A1, 256, nullptr, 0, W, ldw, B, C, ND, 1);
        }
        {   // out: cs_k = relu(concat(a, state) @ ow.T + b)
            const float* A1[4]; const float* A2[4]; const float* W[4]; const float* B[4];
            float* C[4]; int ldw[4];
            for (int k = 0; k < 4; ++k) {
                A1[k] = a + (size_t)k * SD;
                A2[k] = st[k];
                W[k] = g_out_w + (size_t)k * 131072; ldw[k] = 512;
                B[k] = g_out_b + k * 256;
                C[k] = cs + k * 256;
            }
            launch_gemm(4, NROW, 256, 256, A1, 256, A2, 256, W, ldw, B, C, 1024, 1);
        }
        {   // agg split-K x4 -> partials
            const float* A1[4]; const float* W[4]; const float* B[4];
            float* C[4]; int ldw[4];
            for (int z = 0; z < 4; ++z) {
                A1[z] = cs + z * 256;
                W[z] = agg_w + z * 256; ldw[z] = 1024;
                B[z] = nullptr;
                C[z] = aggp + (size_t)z * SD;
            }
            launch_gemm(4, NROW, 256, 0, A1, 1024, nullptr, 0, W, ldw, B, C, ND, 0);
        }
        agg_finish_kernel<<<NROW, 256>>>(agg_b, dec_w, dec_b, outp, P + (size_t)it * SD, it);
    }

    (void)in_sizes; (void)n_in; (void)out_size;
}